// round 1
// baseline (speedup 1.0000x reference)
#include <cuda_runtime.h>
#include <cstdint>

// ---------------------------------------------------------------------------
// RGCN conv with history cache.
//   out[n] = history_buffer[n]                         if history_map[n] != -1
//   out[n] = (1/deg) * sum_r A_r[n] @ W_r              otherwise
// where A_r[n] = sum_{e in edges(n), type(e)==r} x[idx[e]].
// Output duplicated (reference returns (out, out)).
// ---------------------------------------------------------------------------

#define MAX_NODE 100000
#define HID 128
#define NUM_REL 8
#define KDIM (NUM_REL * HID)   // 1024

// Scratch (device globals: no allocation allowed in kernel_launch)
__device__ float g_A[(size_t)MAX_NODE * KDIM];   // compacted per-rel aggregates
__device__ int   g_active[MAX_NODE];             // compacted active node ids
__device__ int   g_count;
__device__ int   g_is64;                         // index dtype: 1 = int64, 0 = int32

// ---------------------------------------------------------------------------
__global__ void detect_reset_kernel(const void* ptrv) {
    g_count = 0;
    // ptr[0] = 0 always. If dtype is int64, 32-bit word[1] is the high half of
    // ptr[0] == 0. If int32, word[1] = ptr[1] = deg(node 0) >= 1 != 0.
    g_is64 = (((const int*)ptrv)[1] == 0) ? 1 : 0;
}

// ---------------------------------------------------------------------------
// One warp per node: copy history row (both output halves) if cached,
// else append node to the active list.
__global__ void compact_history_kernel(const void* __restrict__ hmv,
                                       const float* __restrict__ hb,
                                       float* __restrict__ out,
                                       int dup, int num_node) {
    int w    = (int)((blockIdx.x * blockDim.x + threadIdx.x) >> 5);
    int lane = threadIdx.x & 31;
    if (w >= num_node) return;
    int is64 = g_is64;
    long long m = is64 ? ((const long long*)hmv)[w]
                       : (long long)((const int*)hmv)[w];
    if (m != -1LL) {
        float4 v = *(const float4*)(hb + (size_t)w * HID + lane * 4);
        *(float4*)(out + (size_t)w * HID + lane * 4) = v;
        if (dup)
            *(float4*)(out + (size_t)(w + num_node) * HID + lane * 4) = v;
    } else if (lane == 0) {
        int slot = atomicAdd(&g_count, 1);
        g_active[slot] = w;
    }
}

// ---------------------------------------------------------------------------
// One warp per active node: gather neighbor rows, accumulate per-relation
// sums in registers (lane owns 4 channels), write to g_A.
#define ACC_CASE(r, a)                                                        \
    case r: a.x += v_.x; a.y += v_.y; a.z += v_.z; a.w += v_.w; break;

__global__ void aggregate_kernel(const float* __restrict__ x,
                                 const void* __restrict__ ptrv,
                                 const void* __restrict__ idxv,
                                 const void* __restrict__ etv) {
    int w    = (int)((blockIdx.x * blockDim.x + threadIdx.x) >> 5);
    int lane = threadIdx.x & 31;
    if (w >= g_count) return;
    int is64 = g_is64;
    int node = g_active[w];

    long long p0, p1;
    if (is64) {
        p0 = ((const long long*)ptrv)[node];
        p1 = ((const long long*)ptrv)[node + 1];
    } else {
        p0 = ((const int*)ptrv)[node];
        p1 = ((const int*)ptrv)[node + 1];
    }
    int deg = (int)(p1 - p0);

    float4 a0 = {0,0,0,0}, a1 = {0,0,0,0}, a2 = {0,0,0,0}, a3 = {0,0,0,0};
    float4 a4 = {0,0,0,0}, a5 = {0,0,0,0}, a6 = {0,0,0,0}, a7 = {0,0,0,0};

    // Preload up to 32 edges across lanes (dataset: deg == 16).
    long long s_l = 0; int t_l = 0;
    if (lane < deg) {
        long long e = p0 + lane;
        s_l = is64 ? ((const long long*)idxv)[e]
                   : (long long)((const int*)idxv)[e];
        t_l = is64 ? (int)((const long long*)etv)[e]
                   : ((const int*)etv)[e];
    }
    int dcap = deg < 32 ? deg : 32;

    for (int j0 = 0; j0 < dcap; j0 += 4) {
        float4 v[4]; int tt[4];
        #pragma unroll
        for (int u = 0; u < 4; u++) {
            int j = j0 + u;
            long long src = __shfl_sync(0xffffffffu, s_l, j & 31);
            int      ty   = __shfl_sync(0xffffffffu, t_l, j & 31);
            if (j < dcap) {
                v[u]  = *(const float4*)(x + (size_t)src * HID + lane * 4);
                tt[u] = ty;
            } else {
                v[u] = make_float4(0.f, 0.f, 0.f, 0.f);
                tt[u] = NUM_REL;  // no case matches
            }
        }
        #pragma unroll
        for (int u = 0; u < 4; u++) {
            float4 v_ = v[u];
            switch (tt[u]) {
                ACC_CASE(0, a0) ACC_CASE(1, a1) ACC_CASE(2, a2) ACC_CASE(3, a3)
                ACC_CASE(4, a4) ACC_CASE(5, a5) ACC_CASE(6, a6) ACC_CASE(7, a7)
                default: break;
            }
        }
    }
    // Generic tail (deg > 32) — not hit for this dataset but keeps it correct.
    for (long long e = p0 + 32; e < p1; e++) {
        long long src = is64 ? ((const long long*)idxv)[e]
                             : (long long)((const int*)idxv)[e];
        int ty = is64 ? (int)((const long long*)etv)[e]
                      : ((const int*)etv)[e];
        float4 v_ = *(const float4*)(x + (size_t)src * HID + lane * 4);
        switch (ty) {
            ACC_CASE(0, a0) ACC_CASE(1, a1) ACC_CASE(2, a2) ACC_CASE(3, a3)
            ACC_CASE(4, a4) ACC_CASE(5, a5) ACC_CASE(6, a6) ACC_CASE(7, a7)
            default: break;
        }
    }

    float* base = g_A + (size_t)w * KDIM + lane * 4;
    *(float4*)(base + 0 * HID) = a0;  *(float4*)(base + 1 * HID) = a1;
    *(float4*)(base + 2 * HID) = a2;  *(float4*)(base + 3 * HID) = a3;
    *(float4*)(base + 4 * HID) = a4;  *(float4*)(base + 5 * HID) = a5;
    *(float4*)(base + 6 * HID) = a6;  *(float4*)(base + 7 * HID) = a7;
}

// ---------------------------------------------------------------------------
// Tiled GEMM: out_rows = g_A[count,1024] @ Wflat[1024,128], fused 1/deg scale
// and scatter to both output halves.
// Block tile 64x128, k-tile 32, 256 threads, 8x4 microtile per thread.
#define BM 64
#define BN 128
#define BK 32

__global__ __launch_bounds__(256)
void gemm_out_kernel(const float* __restrict__ W,
                     const void* __restrict__ ptrv,
                     float* __restrict__ out,
                     int dup, int num_node) {
    __shared__ float As[BK][BM + 1];   // +1 pad: conflict-free transposed store
    __shared__ float Bs[BK][BN];

    int count = g_count;
    int m0 = blockIdx.x * BM;
    if (m0 >= count) return;

    int t  = threadIdx.x;
    int tx = t & 31;    // cols tx*4 .. tx*4+3
    int ty = t >> 5;    // rows ty*8 .. ty*8+7

    float acc[8][4];
    #pragma unroll
    for (int i = 0; i < 8; i++)
        #pragma unroll
        for (int j = 0; j < 4; j++) acc[i][j] = 0.f;

    for (int k0 = 0; k0 < KDIM; k0 += BK) {
        // A tile: 64 rows x 32 cols = 512 float4, transposed into As[k][m]
        #pragma unroll
        for (int i = 0; i < 2; i++) {
            int id  = t + i * 256;
            int row = id >> 3;
            int c4  = id & 7;
            float4 v = make_float4(0.f, 0.f, 0.f, 0.f);
            int gm = m0 + row;
            if (gm < count)
                v = *(const float4*)&g_A[(size_t)gm * KDIM + k0 + c4 * 4];
            As[c4 * 4 + 0][row] = v.x;
            As[c4 * 4 + 1][row] = v.y;
            As[c4 * 4 + 2][row] = v.z;
            As[c4 * 4 + 3][row] = v.w;
        }
        // B tile: 32 rows x 128 cols = 1024 float4
        #pragma unroll
        for (int i = 0; i < 4; i++) {
            int id  = t + i * 256;
            int row = id >> 5;
            int c4  = id & 31;
            *(float4*)&Bs[row][c4 * 4] =
                *(const float4*)&W[(size_t)(k0 + row) * BN + c4 * 4];
        }
        __syncthreads();

        #pragma unroll
        for (int k = 0; k < BK; k++) {
            float4 b = *(const float4*)&Bs[k][tx * 4];
            float ar[8];
            #pragma unroll
            for (int i = 0; i < 8; i++) ar[i] = As[k][ty * 8 + i];
            #pragma unroll
            for (int i = 0; i < 8; i++) {
                acc[i][0] += ar[i] * b.x;
                acc[i][1] += ar[i] * b.y;
                acc[i][2] += ar[i] * b.z;
                acc[i][3] += ar[i] * b.w;
            }
        }
        __syncthreads();
    }

    int is64 = g_is64;
    #pragma unroll
    for (int i = 0; i < 8; i++) {
        int m = m0 + ty * 8 + i;
        if (m < count) {
            int node = g_active[m];
            long long d;
            if (is64)
                d = ((const long long*)ptrv)[node + 1] - ((const long long*)ptrv)[node];
            else
                d = (long long)(((const int*)ptrv)[node + 1] - ((const int*)ptrv)[node]);
            float inv = 1.0f / (float)d;
            float4 v = make_float4(acc[i][0] * inv, acc[i][1] * inv,
                                   acc[i][2] * inv, acc[i][3] * inv);
            *(float4*)(out + (size_t)node * HID + tx * 4) = v;
            if (dup)
                *(float4*)(out + (size_t)(node + num_node) * HID + tx * 4) = v;
        }
    }
}

// ---------------------------------------------------------------------------
extern "C" void kernel_launch(void* const* d_in, const int* in_sizes, int n_in,
                              void* d_out, int out_size) {
    const float* x  = (const float*)d_in[0];
    const float* W  = (const float*)d_in[1];   // [8,128,128] == [1024,128] flat
    const void*  pt = d_in[2];
    const void*  ix = d_in[3];
    const void*  et = d_in[4];
    const void*  hm = d_in[5];
    const float* hb = (const float*)d_in[6];
    float* out = (float*)d_out;

    int num_node = in_sizes[0] / HID;
    long long need2 = 2LL * (long long)num_node * HID;
    int dup = ((long long)out_size >= need2) ? 1 : 0;

    detect_reset_kernel<<<1, 1>>>(pt);

    int warp_blocks = (num_node * 32 + 255) / 256;
    compact_history_kernel<<<warp_blocks, 256>>>(hm, hb, out, dup, num_node);
    aggregate_kernel<<<warp_blocks, 256>>>(x, pt, ix, et);
    gemm_out_kernel<<<(num_node + BM - 1) / BM, 256>>>(W, pt, out, dup, num_node);
}

// round 3
// speedup vs baseline: 1.5446x; 1.5446x over previous
#include <cuda_runtime.h>
#include <cuda_bf16.h>
#include <cstdint>

// ---------------------------------------------------------------------------
// RGCN conv with history cache.
//   out[n] = history_buffer[n]                       if history_map[n] != -1
//   out[n] = (1/deg) * sum_r A_r[n] @ W_r            otherwise
// Aggregate per-relation sums into compacted rows (active nodes only), split
// to bf16 hi/lo planes, then GEMM = Ah@Wh + Ah@Wl + Al@Wh with mma.sync
// (tcgen05 is not reachable: harness PTX targets compute_103 without 'a').
// ---------------------------------------------------------------------------

#define MAX_NODE 100000
#define PAD_ROWS (MAX_NODE + 256)
#define HID 128
#define NUM_REL 8
#define KDIM (NUM_REL * HID)   // 1024

__device__ __nv_bfloat16 g_Ah[(size_t)PAD_ROWS * KDIM];
__device__ __nv_bfloat16 g_Al[(size_t)PAD_ROWS * KDIM];
__device__ __nv_bfloat16 g_Wh[(size_t)HID * KDIM];   // [n][k] (K-major)
__device__ __nv_bfloat16 g_Wl[(size_t)HID * KDIM];
__device__ int  g_active[MAX_NODE];
__device__ int  g_count;
__device__ int  g_is64;

// ======================= PTX helpers =======================================
__device__ __forceinline__ uint32_t smem_u32(const void* p) {
    uint32_t a;
    asm("{ .reg .u64 t; cvta.to.shared.u64 t, %1; cvt.u32.u64 %0, t; }"
        : "=r"(a) : "l"(p));
    return a;
}
#define CP16(dst, src) \
    asm volatile("cp.async.cg.shared.global [%0], [%1], 16;" \
        :: "r"(dst), "l"(src) : "memory")
#define CP_COMMIT() asm volatile("cp.async.commit_group;" ::: "memory")
#define CP_WAIT(n)  asm volatile("cp.async.wait_group %0;" :: "n"(n) : "memory")

#define LDSM4(r, a)                                                           \
    asm volatile("ldmatrix.sync.aligned.m8n8.x4.shared.b16 {%0,%1,%2,%3}, [%4];" \
        : "=r"((r)[0]), "=r"((r)[1]), "=r"((r)[2]), "=r"((r)[3]) : "r"(a))

#define MMA16816(c, a, b0, b1)                                                \
    asm volatile("mma.sync.aligned.m16n8k16.row.col.f32.bf16.bf16.f32 "       \
        "{%0,%1,%2,%3}, {%4,%5,%6,%7}, {%8,%9}, {%0,%1,%2,%3};"               \
        : "+f"((c)[0]), "+f"((c)[1]), "+f"((c)[2]), "+f"((c)[3])              \
        : "r"((a)[0]), "r"((a)[1]), "r"((a)[2]), "r"((a)[3]),                 \
          "r"(b0), "r"(b1))

// ===========================================================================
__global__ void detect_reset_kernel(const void* ptrv) {
    g_count = 0;
    // ptr[0]==0; if int64, word[1] is the high half of 0; if int32 it is deg>=1.
    g_is64 = (((const int*)ptrv)[1] == 0) ? 1 : 0;
}

// Split-transpose W [1024,128] fp32 -> g_Wh/g_Wl [128][1024] bf16
__global__ void wprep_kernel(const float* __restrict__ W) {
    int i = blockIdx.x * blockDim.x + threadIdx.x;
    if (i >= KDIM * HID) return;
    int k = i >> 7, n = i & 127;
    float v = W[i];
    __nv_bfloat16 h = __float2bfloat16(v);
    __nv_bfloat16 l = __float2bfloat16(v - __bfloat162float(h));
    g_Wh[(size_t)n * KDIM + k] = h;
    g_Wl[(size_t)n * KDIM + k] = l;
}

// ---------------------------------------------------------------------------
__global__ void compact_history_kernel(const void* __restrict__ hmv,
                                       const float* __restrict__ hb,
                                       float* __restrict__ out,
                                       int dup, int num_node) {
    int w    = (int)((blockIdx.x * blockDim.x + threadIdx.x) >> 5);
    int lane = threadIdx.x & 31;
    if (w >= num_node) return;
    long long m = g_is64 ? ((const long long*)hmv)[w]
                         : (long long)((const int*)hmv)[w];
    if (m != -1LL) {
        float4 v = *(const float4*)(hb + (size_t)w * HID + lane * 4);
        *(float4*)(out + (size_t)w * HID + lane * 4) = v;
        if (dup)
            *(float4*)(out + (size_t)(w + num_node) * HID + lane * 4) = v;
    } else if (lane == 0) {
        int slot = atomicAdd(&g_count, 1);
        g_active[slot] = w;
    }
}

// ---------------------------------------------------------------------------
__device__ __forceinline__ void split_store(float4 a, size_t off) {
    __nv_bfloat16 h0 = __float2bfloat16(a.x), h1 = __float2bfloat16(a.y);
    __nv_bfloat16 h2 = __float2bfloat16(a.z), h3 = __float2bfloat16(a.w);
    __nv_bfloat16 l0 = __float2bfloat16(a.x - __bfloat162float(h0));
    __nv_bfloat16 l1 = __float2bfloat16(a.y - __bfloat162float(h1));
    __nv_bfloat16 l2 = __float2bfloat16(a.z - __bfloat162float(h2));
    __nv_bfloat16 l3 = __float2bfloat16(a.w - __bfloat162float(h3));
    uint2 uh, ul;
    uh.x = ((uint32_t)__bfloat16_as_ushort(h1) << 16) | __bfloat16_as_ushort(h0);
    uh.y = ((uint32_t)__bfloat16_as_ushort(h3) << 16) | __bfloat16_as_ushort(h2);
    ul.x = ((uint32_t)__bfloat16_as_ushort(l1) << 16) | __bfloat16_as_ushort(l0);
    ul.y = ((uint32_t)__bfloat16_as_ushort(l3) << 16) | __bfloat16_as_ushort(l2);
    *(uint2*)((__nv_bfloat16*)g_Ah + off) = uh;
    *(uint2*)((__nv_bfloat16*)g_Al + off) = ul;
}

#define ACC_CASE(r, a)                                                        \
    case r: a.x += v_.x; a.y += v_.y; a.z += v_.z; a.w += v_.w; break;

__global__ void aggregate_kernel(const float* __restrict__ x,
                                 const void* __restrict__ ptrv,
                                 const void* __restrict__ idxv,
                                 const void* __restrict__ etv) {
    int w    = (int)((blockIdx.x * blockDim.x + threadIdx.x) >> 5);
    int lane = threadIdx.x & 31;
    if (w >= g_count) return;
    int is64 = g_is64;
    int node = g_active[w];

    long long p0, p1;
    if (is64) {
        p0 = ((const long long*)ptrv)[node];
        p1 = ((const long long*)ptrv)[node + 1];
    } else {
        p0 = ((const int*)ptrv)[node];
        p1 = ((const int*)ptrv)[node + 1];
    }
    int deg = (int)(p1 - p0);

    float4 a0 = {0,0,0,0}, a1 = {0,0,0,0}, a2 = {0,0,0,0}, a3 = {0,0,0,0};
    float4 a4 = {0,0,0,0}, a5 = {0,0,0,0}, a6 = {0,0,0,0}, a7 = {0,0,0,0};

    long long s_l = 0; int t_l = 0;
    if (lane < deg) {
        long long e = p0 + lane;
        s_l = is64 ? ((const long long*)idxv)[e]
                   : (long long)((const int*)idxv)[e];
        t_l = is64 ? (int)((const long long*)etv)[e]
                   : ((const int*)etv)[e];
    }
    int dcap = deg < 32 ? deg : 32;

    for (int j0 = 0; j0 < dcap; j0 += 4) {
        float4 v[4]; int tt[4];
        #pragma unroll
        for (int u = 0; u < 4; u++) {
            int j = j0 + u;
            long long src = __shfl_sync(0xffffffffu, s_l, j & 31);
            int      ty   = __shfl_sync(0xffffffffu, t_l, j & 31);
            if (j < dcap) {
                v[u]  = *(const float4*)(x + (size_t)src * HID + lane * 4);
                tt[u] = ty;
            } else {
                v[u] = make_float4(0.f, 0.f, 0.f, 0.f);
                tt[u] = NUM_REL;
            }
        }
        #pragma unroll
        for (int u = 0; u < 4; u++) {
            float4 v_ = v[u];
            switch (tt[u]) {
                ACC_CASE(0, a0) ACC_CASE(1, a1) ACC_CASE(2, a2) ACC_CASE(3, a3)
                ACC_CASE(4, a4) ACC_CASE(5, a5) ACC_CASE(6, a6) ACC_CASE(7, a7)
                default: break;
            }
        }
    }
    for (long long e = p0 + 32; e < p1; e++) {   // generic tail (unused here)
        long long src = is64 ? ((const long long*)idxv)[e]
                             : (long long)((const int*)idxv)[e];
        int ty = is64 ? (int)((const long long*)etv)[e]
                      : ((const int*)etv)[e];
        float4 v_ = *(const float4*)(x + (size_t)src * HID + lane * 4);
        switch (ty) {
            ACC_CASE(0, a0) ACC_CASE(1, a1) ACC_CASE(2, a2) ACC_CASE(3, a3)
            ACC_CASE(4, a4) ACC_CASE(5, a5) ACC_CASE(6, a6) ACC_CASE(7, a7)
            default: break;
        }
    }

    size_t base = (size_t)w * KDIM + lane * 4;
    split_store(a0, base + 0 * HID);  split_store(a1, base + 1 * HID);
    split_store(a2, base + 2 * HID);  split_store(a3, base + 3 * HID);
    split_store(a4, base + 4 * HID);  split_store(a5, base + 5 * HID);
    split_store(a6, base + 6 * HID);  split_store(a7, base + 7 * HID);
}

// ---------------------------------------------------------------------------
// mma.sync GEMM: [count,1024](Ah,Al) @ [1024,128](Wh,Wl), 3-term split.
// CTA 128x128, 8 warps (2x4), warp 64x32, k-tile 64, double-buffered cp.async.
#define GBM 128
#define GBK 64
#define NT (KDIM / GBK)                // 16 k-tiles
#define TP (GBM * GBK * 2)             // 16384 bytes per plane tile
#define S_AH 0
#define S_AL TP
#define S_BH (2 * TP)
#define S_BL (3 * TP)
#define STAGE_B (4 * TP)               // 65536 per stage
#define SMEM_BYTES (2 * STAGE_B)

// swizzled byte offset within a [rows][64 bf16] tile (row stride 128B, SW128)
__device__ __forceinline__ uint32_t swz(uint32_t row, uint32_t chunk) {
    return row * 128u + ((chunk ^ (row & 7u)) << 4);
}

__global__ __launch_bounds__(256)
void gemm_mma_kernel(const void* __restrict__ ptrv,
                     float* __restrict__ out,
                     int dup, int num_node) {
    extern __shared__ __align__(1024) char smem[];
    int count = g_count;
    int m0 = blockIdx.x * GBM;
    if (m0 >= count) return;

    uint32_t sb = smem_u32(smem);
    int t = threadIdx.x, wid = t >> 5, lane = t & 31;
    int wm = wid >> 2;                 // 0..1  (m block of 64)
    int wn = wid & 3;                  // 0..3  (n block of 32)

    const __nv_bfloat16* pAh = (const __nv_bfloat16*)g_Ah;
    const __nv_bfloat16* pAl = (const __nv_bfloat16*)g_Al;
    const __nv_bfloat16* pWh = (const __nv_bfloat16*)g_Wh;
    const __nv_bfloat16* pWl = (const __nv_bfloat16*)g_Wl;

    // ldmatrix lane-role: tile index and row within 8x8 tile
    int ltile = lane >> 3, lrow = lane & 7;

    float acc[4][4][4];
    #pragma unroll
    for (int i = 0; i < 4; i++)
        #pragma unroll
        for (int j = 0; j < 4; j++)
            #pragma unroll
            for (int q = 0; q < 4; q++) acc[i][j][q] = 0.f;

    // ---- stage loader ----
    auto load_stage = [&](int kt) {
        uint32_t stg = sb + (kt & 1) * STAGE_B;
        size_t kofs = (size_t)kt * GBK;
        #pragma unroll
        for (int i = 0; i < 4; i++) {
            int id  = t + i * 256;          // 0..1023
            int row = id >> 3;              // 0..127
            int c   = id & 7;
            uint32_t sw = swz(row, c);
            size_t ga = (size_t)(m0 + row) * KDIM + kofs + c * 8;
            size_t gw = (size_t)row * KDIM + kofs + c * 8;
            CP16(stg + S_AH + sw, pAh + ga);
            CP16(stg + S_AL + sw, pAl + ga);
            CP16(stg + S_BH + sw, pWh + gw);
            CP16(stg + S_BL + sw, pWl + gw);
        }
        CP_COMMIT();
    };

    load_stage(0);

    for (int kt = 0; kt < NT; kt++) {
        if (kt + 1 < NT) { load_stage(kt + 1); CP_WAIT(1); }
        else            { CP_WAIT(0); }
        __syncthreads();

        uint32_t stg = sb + (kt & 1) * STAGE_B;
        #pragma unroll
        for (int ks = 0; ks < 4; ks++) {
            // chunk column for this lane's ldmatrix tile: k16 = 2 chunks
            int cch = ks * 2 + (ltile >> 1);
            // --- A fragments (4 m16 frags per plane) ---
            uint32_t ah[4][4], al[4][4];
            #pragma unroll
            for (int mf = 0; mf < 4; mf++) {
                uint32_t r = wm * 64 + mf * 16 + (ltile & 1) * 8 + lrow;
                uint32_t sw = swz(r, (uint32_t)cch);
                LDSM4(ah[mf], stg + S_AH + sw);
                LDSM4(al[mf], stg + S_AL + sw);
            }
            // --- B fragments: two x4 loads (n16 each) per plane ---
            uint32_t bh[2][4], bl[2][4];
            #pragma unroll
            for (int j = 0; j < 2; j++) {
                uint32_t r = wn * 32 + j * 16 + (ltile & 1) * 8 + lrow;
                uint32_t sw = swz(r, (uint32_t)cch);
                LDSM4(bh[j], stg + S_BH + sw);
                LDSM4(bl[j], stg + S_BL + sw);
            }
            // --- MMAs: acc += Ah*Bh + Ah*Bl + Al*Bh ---
            #pragma unroll
            for (int mf = 0; mf < 4; mf++) {
                #pragma unroll
                for (int nf = 0; nf < 4; nf++) {
                    int hj = nf >> 1, ho = nf & 1;
                    MMA16816(acc[mf][nf], ah[mf], bh[hj][ho], bh[hj][ho + 2]);
                    MMA16816(acc[mf][nf], ah[mf], bl[hj][ho], bl[hj][ho + 2]);
                    MMA16816(acc[mf][nf], al[mf], bh[hj][ho], bh[hj][ho + 2]);
                }
            }
        }
        __syncthreads();
    }

    // ---- epilogue: 1/deg scale + scatter (both output halves) ----
    int g  = lane >> 2;
    int tq = lane & 3;
    int is64 = g_is64;
    #pragma unroll
    for (int mf = 0; mf < 4; mf++) {
        int m_lo = m0 + wm * 64 + mf * 16 + g;       // rows g and g+8
        #pragma unroll
        for (int half = 0; half < 2; half++) {
            int m = m_lo + half * 8;
            if (m >= count) continue;
            int node = g_active[m];
            long long d;
            if (is64)
                d = ((const long long*)ptrv)[node + 1] - ((const long long*)ptrv)[node];
            else
                d = (long long)(((const int*)ptrv)[node + 1] - ((const int*)ptrv)[node]);
            float inv = 1.0f / (float)d;
            #pragma unroll
            for (int nf = 0; nf < 4; nf++) {
                float2 v;
                v.x = acc[mf][nf][half * 2 + 0] * inv;
                v.y = acc[mf][nf][half * 2 + 1] * inv;
                size_t co = (size_t)node * HID + wn * 32 + nf * 8 + tq * 2;
                *(float2*)(out + co) = v;
                if (dup)
                    *(float2*)(out + co + (size_t)num_node * HID) = v;
            }
        }
    }
}

// ---------------------------------------------------------------------------
extern "C" void kernel_launch(void* const* d_in, const int* in_sizes, int n_in,
                              void* d_out, int out_size) {
    const float* x  = (const float*)d_in[0];
    const float* W  = (const float*)d_in[1];   // [8,128,128] == [1024,128]
    const void*  pt = d_in[2];
    const void*  ix = d_in[3];
    const void*  et = d_in[4];
    const void*  hm = d_in[5];
    const float* hb = (const float*)d_in[6];
    float* out = (float*)d_out;

    int num_node = in_sizes[0] / HID;
    long long need2 = 2LL * (long long)num_node * HID;
    int dup = ((long long)out_size >= need2) ? 1 : 0;

    cudaFuncSetAttribute(gemm_mma_kernel,
                         cudaFuncAttributeMaxDynamicSharedMemorySize, SMEM_BYTES);

    detect_reset_kernel<<<1, 1>>>(pt);
    wprep_kernel<<<(KDIM * HID + 255) / 256, 256>>>(W);

    int warp_blocks = (num_node * 32 + 255) / 256;
    compact_history_kernel<<<warp_blocks, 256>>>(hm, hb, out, dup, num_node);
    aggregate_kernel<<<warp_blocks, 256>>>(x, pt, ix, et);
    gemm_mma_kernel<<<(num_node + GBM - 1) / GBM, 256, SMEM_BYTES>>>(
        pt, out, dup, num_node);
}